// round 6
// baseline (speedup 1.0000x reference)
#include <cuda_runtime.h>

// ---------------- problem constants ----------------
#define Nn   50000
#define Ee   1000000
#define HIDc 32
#define OUTc 16
#define H1c  4
#define F1c  128      // H1*HID
#define F2c  16       // H2*OUT
#define NEG  0.2f
#define LNEPS 1e-5f

// ---------------- device scratch (static, no allocation) ----------------
__device__ int      g_is64;
__device__ int      g_src[Ee];
__device__ int      g_dst[Ee];
__device__ float4   g_logit1[Ee];        // 4 head logits per edge
__device__ unsigned g_amax1[Nn * 4];     // encoded float max per (node, head)
__device__ float4   g_denom1[Nn];        // 4 heads packed
__device__ float4   g_agg1[Nn * 32];     // 128 floats per node
__device__ float    g_h[Nn * HIDc];      // layer-1 output features
__device__ float    g_xl2[Nn * F2c];
__device__ float    g_xr2[Nn * F2c];
__device__ float    g_logit2[Ee];
__device__ unsigned g_amax2[Nn];
__device__ float    g_denom2[Nn];
__device__ float4   g_agg2[Nn * 4];      // 16 floats per node

// ---------------- helpers ----------------
__device__ __forceinline__ unsigned fenc(float f) {
    unsigned u = __float_as_uint(f);
    return (u & 0x80000000u) ? ~u : (u | 0x80000000u);
}
__device__ __forceinline__ float fdec(unsigned u) {
    return (u & 0x80000000u) ? __uint_as_float(u & 0x7FFFFFFFu)
                             : __uint_as_float(~u);
}
__device__ __forceinline__ float wsum(float v) {
    #pragma unroll
    for (int o = 16; o; o >>= 1) v += __shfl_xor_sync(0xffffffffu, v, o);
    return v;
}

// ---------------- kernels ----------------

// Detect whether edge_index is int64 (high 32-bit words all zero) or int32.
__global__ void k_detect(const unsigned* __restrict__ ei) {
    unsigned acc = 0u;
    for (int i = 1; i < 256; i += 2) acc |= ei[i];
    g_is64 = (acc == 0u) ? 1 : 0;
}

__global__ void k_decode(const void* __restrict__ ei) {
    int e = blockIdx.x * blockDim.x + threadIdx.x;
    if (e >= Ee) return;
    if (g_is64) {
        const long long* p = (const long long*)ei;
        g_src[e] = (int)p[e];
        g_dst[e] = (int)p[Ee + e];
    } else {
        const int* p = (const int*)ei;
        g_src[e] = p[e];
        g_dst[e] = p[Ee + e];
    }
}

__global__ void k_zero() {
    int i = blockIdx.x * blockDim.x + threadIdx.x;
    int stride = gridDim.x * blockDim.x;
    float4 z4 = make_float4(0.f, 0.f, 0.f, 0.f);
    for (int j = i; j < Nn * 32; j += stride) g_agg1[j] = z4;
    for (int j = i; j < Nn * 4;  j += stride) { g_amax1[j] = 0u; if (j < Nn*4) g_agg2[j] = z4; }
    for (int j = i; j < Nn;      j += stride) {
        g_denom1[j] = z4; g_denom2[j] = 0.f; g_amax2[j] = 0u;
    }
}

// Layer 1, pass A: per-edge attention logits + segment max. xl/xr recomputed
// from the 2-wide input features (rank-2 GEMV), weights in shared.
__global__ void k_edge_logits1(const float* __restrict__ x,
                               const float* __restrict__ ea,
                               const float* __restrict__ W1l, const float* __restrict__ b1l,
                               const float* __restrict__ W1r, const float* __restrict__ b1r,
                               const float* __restrict__ We1, const float* __restrict__ att1) {
    __shared__ float sWl[256], sWr[256], sbl[128], sbr[128], sWe[128], sat[128];
    int t = threadIdx.x;
    sWl[t] = W1l[t]; sWr[t] = W1r[t];
    if (t < 128) { sbl[t] = b1l[t]; sbr[t] = b1r[t]; sWe[t] = We1[t]; sat[t] = att1[t]; }
    __syncthreads();

    int e = blockIdx.x * blockDim.x + t;
    if (e >= Ee) return;
    int s = g_src[e], d = g_dst[e];
    float xs0 = x[2*s], xs1 = x[2*s+1];
    float xd0 = x[2*d], xd1 = x[2*d+1];
    float eav = ea[e];

    float lg[4];
    #pragma unroll
    for (int h = 0; h < 4; h++) {
        float acc = 0.f;
        #pragma unroll
        for (int cc = 0; cc < 32; cc++) {
            int f = h * 32 + cc;
            float xl = fmaf(xs0, sWl[f], fmaf(xs1, sWl[128 + f], sbl[f]));
            float xr = fmaf(xd0, sWr[f], fmaf(xd1, sWr[128 + f], sbr[f]));
            float m  = fmaf(eav, sWe[f], xl + xr);
            m = fmaxf(m, NEG * m);             // LeakyReLU(0.2)
            acc = fmaf(m, sat[f], acc);
        }
        lg[h] = acc;
    }
    g_logit1[e] = make_float4(lg[0], lg[1], lg[2], lg[3]);
    #pragma unroll
    for (int h = 0; h < 4; h++)
        atomicMax(&g_amax1[d * 4 + h], fenc(lg[h]));
}

// Layer 1, pass B: exp, denominator sum, unnormalized weighted aggregation.
__global__ void k_edge_agg1(const float* __restrict__ x,
                            const float* __restrict__ W1l, const float* __restrict__ b1l) {
    __shared__ float sWl[256], sbl[128];
    int t = threadIdx.x;
    sWl[t] = W1l[t];
    if (t < 128) sbl[t] = b1l[t];
    __syncthreads();

    int e = blockIdx.x * blockDim.x + t;
    if (e >= Ee) return;
    int s = g_src[e], d = g_dst[e];

    float4 lg = g_logit1[e];
    const uint4* am4 = (const uint4*)&g_amax1[d * 4];
    uint4 am = *am4;
    float ex[4];
    ex[0] = __expf(lg.x - fdec(am.x));
    ex[1] = __expf(lg.y - fdec(am.y));
    ex[2] = __expf(lg.z - fdec(am.z));
    ex[3] = __expf(lg.w - fdec(am.w));
    atomicAdd(&g_denom1[d], make_float4(ex[0], ex[1], ex[2], ex[3]));

    float xs0 = x[2*s], xs1 = x[2*s+1];
    float4* agg = &g_agg1[d * 32];
    #pragma unroll
    for (int h = 0; h < 4; h++) {
        float exh = ex[h];
        #pragma unroll
        for (int q = 0; q < 8; q++) {
            int f = h * 32 + q * 4;
            float v0 = exh * fmaf(xs0, sWl[f+0], fmaf(xs1, sWl[128+f+0], sbl[f+0]));
            float v1 = exh * fmaf(xs0, sWl[f+1], fmaf(xs1, sWl[128+f+1], sbl[f+1]));
            float v2 = exh * fmaf(xs0, sWl[f+2], fmaf(xs1, sWl[128+f+2], sbl[f+2]));
            float v3 = exh * fmaf(xs0, sWl[f+3], fmaf(xs1, sWl[128+f+3], sbl[f+3]));
            atomicAdd(&agg[h * 8 + q], make_float4(v0, v1, v2, v3));
        }
    }
}

// Layer 1 epilogue: normalize, head-mean, bias, LayerNorm, ELU. Warp per node.
__global__ void k_finish1(const float* __restrict__ bias1,
                          const float* __restrict__ g1,
                          const float* __restrict__ beta1) {
    int gt   = blockIdx.x * blockDim.x + threadIdx.x;
    int node = gt >> 5;
    int lane = gt & 31;
    if (node >= Nn) return;

    float4 den = g_denom1[node];
    float i0 = 1.f / (den.x + 1e-16f);
    float i1 = 1.f / (den.y + 1e-16f);
    float i2 = 1.f / (den.z + 1e-16f);
    float i3 = 1.f / (den.w + 1e-16f);

    const float* agg = (const float*)&g_agg1[node * 32];   // 128 floats
    float v = agg[0*32 + lane] * i0 + agg[1*32 + lane] * i1
            + agg[2*32 + lane] * i2 + agg[3*32 + lane] * i3;
    v = 0.25f * v + bias1[lane];

    float mu  = wsum(v) * (1.f / 32.f);
    float dv  = v - mu;
    float var = wsum(dv * dv) * (1.f / 32.f);
    float y   = dv * rsqrtf(var + LNEPS) * g1[lane] + beta1[lane];
    y = (y > 0.f) ? y : expm1f(y);                          // ELU
    g_h[node * 32 + lane] = y;
}

// Layer 2 node transform: xl2 / xr2 (32 -> 16 GEMV x2). Thread per (node, out).
__global__ void k_transform2(const float* __restrict__ W2l, const float* __restrict__ b2l,
                             const float* __restrict__ W2r, const float* __restrict__ b2r) {
    __shared__ float sWl[512], sWr[512], sbl[16], sbr[16];
    for (int j = threadIdx.x; j < 512; j += blockDim.x) { sWl[j] = W2l[j]; sWr[j] = W2r[j]; }
    if (threadIdx.x < 16) { sbl[threadIdx.x] = b2l[threadIdx.x]; sbr[threadIdx.x] = b2r[threadIdx.x]; }
    __syncthreads();

    int idx = blockIdx.x * blockDim.x + threadIdx.x;
    if (idx >= Nn * 16) return;
    int n = idx >> 4, o = idx & 15;
    const float* hh = &g_h[n * 32];
    float al = sbl[o], ar = sbr[o];
    #pragma unroll
    for (int c = 0; c < 32; c++) {
        float hv = hh[c];
        al = fmaf(hv, sWl[c * 16 + o], al);
        ar = fmaf(hv, sWr[c * 16 + o], ar);
    }
    g_xl2[idx] = al;
    g_xr2[idx] = ar;
}

// Layer 2, pass A: logits + segment max (H2=1).
__global__ void k_edge_logits2(const float* __restrict__ ea,
                               const float* __restrict__ We2,
                               const float* __restrict__ att2) {
    __shared__ float sWe[16], sat[16];
    if (threadIdx.x < 16) { sWe[threadIdx.x] = We2[threadIdx.x]; sat[threadIdx.x] = att2[threadIdx.x]; }
    __syncthreads();

    int e = blockIdx.x * blockDim.x + threadIdx.x;
    if (e >= Ee) return;
    int s = g_src[e], d = g_dst[e];
    float eav = ea[e];
    const float4* xl = (const float4*)&g_xl2[s * 16];
    const float4* xr = (const float4*)&g_xr2[d * 16];

    float acc = 0.f;
    #pragma unroll
    for (int q = 0; q < 4; q++) {
        float4 a = xl[q], b = xr[q];
        float m;
        m = fmaf(eav, sWe[4*q+0], a.x + b.x); m = fmaxf(m, NEG*m); acc = fmaf(m, sat[4*q+0], acc);
        m = fmaf(eav, sWe[4*q+1], a.y + b.y); m = fmaxf(m, NEG*m); acc = fmaf(m, sat[4*q+1], acc);
        m = fmaf(eav, sWe[4*q+2], a.z + b.z); m = fmaxf(m, NEG*m); acc = fmaf(m, sat[4*q+2], acc);
        m = fmaf(eav, sWe[4*q+3], a.w + b.w); m = fmaxf(m, NEG*m); acc = fmaf(m, sat[4*q+3], acc);
    }
    g_logit2[e] = acc;
    atomicMax(&g_amax2[d], fenc(acc));
}

// Layer 2, pass B: exp, denom, weighted aggregation.
__global__ void k_edge_agg2() {
    int e = blockIdx.x * blockDim.x + threadIdx.x;
    if (e >= Ee) return;
    int s = g_src[e], d = g_dst[e];
    float ex = __expf(g_logit2[e] - fdec(g_amax2[d]));
    atomicAdd(&g_denom2[d], ex);
    const float4* xl = (const float4*)&g_xl2[s * 16];
    float4* agg = &g_agg2[d * 4];
    #pragma unroll
    for (int q = 0; q < 4; q++) {
        float4 a = xl[q];
        atomicAdd(&agg[q], make_float4(ex*a.x, ex*a.y, ex*a.z, ex*a.w));
    }
}

// Layer 2 epilogue: normalize + bias + LayerNorm -> output. Thread per node.
__global__ void k_finish2(const float* __restrict__ bias2,
                          const float* __restrict__ g2,
                          const float* __restrict__ beta2,
                          float* __restrict__ out) {
    int n = blockIdx.x * blockDim.x + threadIdx.x;
    if (n >= Nn) return;
    float inv = 1.f / (g_denom2[n] + 1e-16f);
    const float* agg = (const float*)&g_agg2[n * 4];
    float z[16];
    float mu = 0.f;
    #pragma unroll
    for (int c = 0; c < 16; c++) { z[c] = agg[c] * inv + bias2[c]; mu += z[c]; }
    mu *= (1.f / 16.f);
    float var = 0.f;
    #pragma unroll
    for (int c = 0; c < 16; c++) { float dd = z[c] - mu; var += dd * dd; }
    var *= (1.f / 16.f);
    float r = rsqrtf(var + LNEPS);
    #pragma unroll
    for (int c = 0; c < 16; c++)
        out[n * 16 + c] = (z[c] - mu) * r * g2[c] + beta2[c];
}

// ---------------- launch ----------------
extern "C" void kernel_launch(void* const* d_in, const int* in_sizes, int n_in,
                              void* d_out, int out_size) {
    const float* x     = (const float*)d_in[0];
    const void*  ei    = d_in[1];
    const float* ea    = (const float*)d_in[2];
    const float* W1l   = (const float*)d_in[3];
    const float* b1l   = (const float*)d_in[4];
    const float* W1r   = (const float*)d_in[5];
    const float* b1r   = (const float*)d_in[6];
    const float* We1   = (const float*)d_in[7];
    const float* att1  = (const float*)d_in[8];
    const float* bias1 = (const float*)d_in[9];
    const float* g1    = (const float*)d_in[10];
    const float* beta1 = (const float*)d_in[11];
    const float* W2l   = (const float*)d_in[12];
    const float* b2l   = (const float*)d_in[13];
    const float* W2r   = (const float*)d_in[14];
    const float* b2r   = (const float*)d_in[15];
    const float* We2   = (const float*)d_in[16];
    const float* att2  = (const float*)d_in[17];
    const float* bias2 = (const float*)d_in[18];
    const float* g2    = (const float*)d_in[19];
    const float* beta2 = (const float*)d_in[20];
    float* out = (float*)d_out;

    const int TB = 256;
    const int EB = (Ee + TB - 1) / TB;

    k_detect<<<1, 1>>>((const unsigned*)ei);
    k_decode<<<EB, TB>>>(ei);
    k_zero<<<4096, TB>>>();

    k_edge_logits1<<<EB, TB>>>(x, ea, W1l, b1l, W1r, b1r, We1, att1);
    k_edge_agg1<<<EB, TB>>>(x, W1l, b1l);
    k_finish1<<<(Nn * 32) / TB, TB>>>(bias1, g1, beta1);

    k_transform2<<<(Nn * 16 + TB - 1) / TB, TB>>>(W2l, b2l, W2r, b2r);
    k_edge_logits2<<<EB, TB>>>(ea, We2, att2);
    k_edge_agg2<<<EB, TB>>>();
    k_finish2<<<(Nn + TB - 1) / TB, TB>>>(bias2, g2, beta2, out);
}

// round 7
// speedup vs baseline: 1.0046x; 1.0046x over previous
#include <cuda_runtime.h>

// ---------------- problem constants ----------------
#define Nn   50000
#define Ee   1000000
#define HIDc 32
#define OUTc 16
#define H1c  4
#define F1c  128      // H1*HID
#define F2c  16       // H2*OUT
#define NEG  0.2f
#define LNEPS 1e-5f

// ---------------- device scratch (static, no allocation) ----------------
__device__ int      g_is64;
__device__ int      g_src[Ee];
__device__ int      g_dst[Ee];
__device__ float4   g_logit1[Ee];        // 4 head logits per edge
__device__ unsigned g_amax1[Nn * 4];     // encoded float max per (node, head)
__device__ float4   g_denom1[Nn];        // 4 heads packed
__device__ float4   g_agg1[Nn * 32];     // 128 floats per node
__device__ float    g_h[Nn * HIDc];      // layer-1 output features
__device__ float    g_xl2[Nn * F2c];
__device__ float    g_xr2[Nn * F2c];
__device__ float    g_logit2[Ee];
__device__ unsigned g_amax2[Nn];
__device__ float    g_denom2[Nn];
__device__ float4   g_agg2[Nn * 4];      // 16 floats per node

// ---------------- helpers ----------------
__device__ __forceinline__ unsigned fenc(float f) {
    unsigned u = __float_as_uint(f);
    return (u & 0x80000000u) ? ~u : (u | 0x80000000u);
}
__device__ __forceinline__ float fdec(unsigned u) {
    return (u & 0x80000000u) ? __uint_as_float(u & 0x7FFFFFFFu)
                             : __uint_as_float(~u);
}
__device__ __forceinline__ float wsum(float v) {
    #pragma unroll
    for (int o = 16; o; o >>= 1) v += __shfl_xor_sync(0xffffffffu, v, o);
    return v;
}

// ---------------- kernels ----------------

// Detect whether edge_index is int64 (high 32-bit words all zero) or int32.
__global__ void k_detect(const unsigned* __restrict__ ei) {
    unsigned acc = 0u;
    for (int i = 1; i < 256; i += 2) acc |= ei[i];
    g_is64 = (acc == 0u) ? 1 : 0;
}

__global__ void k_decode(const void* __restrict__ ei) {
    int e = blockIdx.x * blockDim.x + threadIdx.x;
    if (e >= Ee) return;
    if (g_is64) {
        const long long* p = (const long long*)ei;
        g_src[e] = (int)p[e];
        g_dst[e] = (int)p[Ee + e];
    } else {
        const int* p = (const int*)ei;
        g_src[e] = p[e];
        g_dst[e] = p[Ee + e];
    }
}

__global__ void k_zero() {
    int i = blockIdx.x * blockDim.x + threadIdx.x;
    int stride = gridDim.x * blockDim.x;
    float4 z4 = make_float4(0.f, 0.f, 0.f, 0.f);
    for (int j = i; j < Nn * 32; j += stride) g_agg1[j] = z4;
    for (int j = i; j < Nn * 4;  j += stride) { g_amax1[j] = 0u; if (j < Nn*4) g_agg2[j] = z4; }
    for (int j = i; j < Nn;      j += stride) {
        g_denom1[j] = z4; g_denom2[j] = 0.f; g_amax2[j] = 0u;
    }
}

// Layer 1, pass A: per-edge attention logits + segment max. xl/xr recomputed
// from the 2-wide input features (rank-2 GEMV), weights in shared.
__global__ void k_edge_logits1(const float* __restrict__ x,
                               const float* __restrict__ ea,
                               const float* __restrict__ W1l, const float* __restrict__ b1l,
                               const float* __restrict__ W1r, const float* __restrict__ b1r,
                               const float* __restrict__ We1, const float* __restrict__ att1) {
    __shared__ float sWl[256], sWr[256], sbl[128], sbr[128], sWe[128], sat[128];
    int t = threadIdx.x;
    sWl[t] = W1l[t]; sWr[t] = W1r[t];
    if (t < 128) { sbl[t] = b1l[t]; sbr[t] = b1r[t]; sWe[t] = We1[t]; sat[t] = att1[t]; }
    __syncthreads();

    int e = blockIdx.x * blockDim.x + t;
    if (e >= Ee) return;
    int s = g_src[e], d = g_dst[e];
    float xs0 = x[2*s], xs1 = x[2*s+1];
    float xd0 = x[2*d], xd1 = x[2*d+1];
    float eav = ea[e];

    float lg[4];
    #pragma unroll
    for (int h = 0; h < 4; h++) {
        float acc = 0.f;
        #pragma unroll
        for (int cc = 0; cc < 32; cc++) {
            int f = h * 32 + cc;
            float xl = fmaf(xs0, sWl[f], fmaf(xs1, sWl[128 + f], sbl[f]));
            float xr = fmaf(xd0, sWr[f], fmaf(xd1, sWr[128 + f], sbr[f]));
            float m  = fmaf(eav, sWe[f], xl + xr);
            m = fmaxf(m, NEG * m);             // LeakyReLU(0.2)
            acc = fmaf(m, sat[f], acc);
        }
        lg[h] = acc;
    }
    g_logit1[e] = make_float4(lg[0], lg[1], lg[2], lg[3]);
    #pragma unroll
    for (int h = 0; h < 4; h++)
        atomicMax(&g_amax1[d * 4 + h], fenc(lg[h]));
}

// Layer 1, pass B: exp, denominator sum, unnormalized weighted aggregation.
__global__ void k_edge_agg1(const float* __restrict__ x,
                            const float* __restrict__ W1l, const float* __restrict__ b1l) {
    __shared__ float sWl[256], sbl[128];
    int t = threadIdx.x;
    sWl[t] = W1l[t];
    if (t < 128) sbl[t] = b1l[t];
    __syncthreads();

    int e = blockIdx.x * blockDim.x + t;
    if (e >= Ee) return;
    int s = g_src[e], d = g_dst[e];

    float4 lg = g_logit1[e];
    const uint4* am4 = (const uint4*)&g_amax1[d * 4];
    uint4 am = *am4;
    float ex[4];
    ex[0] = __expf(lg.x - fdec(am.x));
    ex[1] = __expf(lg.y - fdec(am.y));
    ex[2] = __expf(lg.z - fdec(am.z));
    ex[3] = __expf(lg.w - fdec(am.w));
    atomicAdd(&g_denom1[d], make_float4(ex[0], ex[1], ex[2], ex[3]));

    float xs0 = x[2*s], xs1 = x[2*s+1];
    float4* agg = &g_agg1[d * 32];
    #pragma unroll
    for (int h = 0; h < 4; h++) {
        float exh = ex[h];
        #pragma unroll
        for (int q = 0; q < 8; q++) {
            int f = h * 32 + q * 4;
            float v0 = exh * fmaf(xs0, sWl[f+0], fmaf(xs1, sWl[128+f+0], sbl[f+0]));
            float v1 = exh * fmaf(xs0, sWl[f+1], fmaf(xs1, sWl[128+f+1], sbl[f+1]));
            float v2 = exh * fmaf(xs0, sWl[f+2], fmaf(xs1, sWl[128+f+2], sbl[f+2]));
            float v3 = exh * fmaf(xs0, sWl[f+3], fmaf(xs1, sWl[128+f+3], sbl[f+3]));
            atomicAdd(&agg[h * 8 + q], make_float4(v0, v1, v2, v3));
        }
    }
}

// Layer 1 epilogue: normalize, head-mean, bias, LayerNorm, ELU. Warp per node.
__global__ void k_finish1(const float* __restrict__ bias1,
                          const float* __restrict__ g1,
                          const float* __restrict__ beta1) {
    int gt   = blockIdx.x * blockDim.x + threadIdx.x;
    int node = gt >> 5;
    int lane = gt & 31;
    if (node >= Nn) return;

    float4 den = g_denom1[node];
    float i0 = 1.f / (den.x + 1e-16f);
    float i1 = 1.f / (den.y + 1e-16f);
    float i2 = 1.f / (den.z + 1e-16f);
    float i3 = 1.f / (den.w + 1e-16f);

    const float* agg = (const float*)&g_agg1[node * 32];   // 128 floats
    float v = agg[0*32 + lane] * i0 + agg[1*32 + lane] * i1
            + agg[2*32 + lane] * i2 + agg[3*32 + lane] * i3;
    v = 0.25f * v + bias1[lane];

    float mu  = wsum(v) * (1.f / 32.f);
    float dv  = v - mu;
    float var = wsum(dv * dv) * (1.f / 32.f);
    float y   = dv * rsqrtf(var + LNEPS) * g1[lane] + beta1[lane];
    y = (y > 0.f) ? y : expm1f(y);                          // ELU
    g_h[node * 32 + lane] = y;
}

// Layer 2 node transform: xl2 / xr2 (32 -> 16 GEMV x2). Thread per (node, out).
__global__ void k_transform2(const float* __restrict__ W2l, const float* __restrict__ b2l,
                             const float* __restrict__ W2r, const float* __restrict__ b2r) {
    __shared__ float sWl[512], sWr[512], sbl[16], sbr[16];
    for (int j = threadIdx.x; j < 512; j += blockDim.x) { sWl[j] = W2l[j]; sWr[j] = W2r[j]; }
    if (threadIdx.x < 16) { sbl[threadIdx.x] = b2l[threadIdx.x]; sbr[threadIdx.x] = b2r[threadIdx.x]; }
    __syncthreads();

    int idx = blockIdx.x * blockDim.x + threadIdx.x;
    if (idx >= Nn * 16) return;
    int n = idx >> 4, o = idx & 15;
    const float* hh = &g_h[n * 32];
    float al = sbl[o], ar = sbr[o];
    #pragma unroll
    for (int c = 0; c < 32; c++) {
        float hv = hh[c];
        al = fmaf(hv, sWl[c * 16 + o], al);
        ar = fmaf(hv, sWr[c * 16 + o], ar);
    }
    g_xl2[idx] = al;
    g_xr2[idx] = ar;
}

// Layer 2, pass A: logits + segment max (H2=1).
__global__ void k_edge_logits2(const float* __restrict__ ea,
                               const float* __restrict__ We2,
                               const float* __restrict__ att2) {
    __shared__ float sWe[16], sat[16];
    if (threadIdx.x < 16) { sWe[threadIdx.x] = We2[threadIdx.x]; sat[threadIdx.x] = att2[threadIdx.x]; }
    __syncthreads();

    int e = blockIdx.x * blockDim.x + threadIdx.x;
    if (e >= Ee) return;
    int s = g_src[e], d = g_dst[e];
    float eav = ea[e];
    const float4* xl = (const float4*)&g_xl2[s * 16];
    const float4* xr = (const float4*)&g_xr2[d * 16];

    float acc = 0.f;
    #pragma unroll
    for (int q = 0; q < 4; q++) {
        float4 a = xl[q], b = xr[q];
        float m;
        m = fmaf(eav, sWe[4*q+0], a.x + b.x); m = fmaxf(m, NEG*m); acc = fmaf(m, sat[4*q+0], acc);
        m = fmaf(eav, sWe[4*q+1], a.y + b.y); m = fmaxf(m, NEG*m); acc = fmaf(m, sat[4*q+1], acc);
        m = fmaf(eav, sWe[4*q+2], a.z + b.z); m = fmaxf(m, NEG*m); acc = fmaf(m, sat[4*q+2], acc);
        m = fmaf(eav, sWe[4*q+3], a.w + b.w); m = fmaxf(m, NEG*m); acc = fmaf(m, sat[4*q+3], acc);
    }
    g_logit2[e] = acc;
    atomicMax(&g_amax2[d], fenc(acc));
}

// Layer 2, pass B: exp, denom, weighted aggregation.
__global__ void k_edge_agg2() {
    int e = blockIdx.x * blockDim.x + threadIdx.x;
    if (e >= Ee) return;
    int s = g_src[e], d = g_dst[e];
    float ex = __expf(g_logit2[e] - fdec(g_amax2[d]));
    atomicAdd(&g_denom2[d], ex);
    const float4* xl = (const float4*)&g_xl2[s * 16];
    float4* agg = &g_agg2[d * 4];
    #pragma unroll
    for (int q = 0; q < 4; q++) {
        float4 a = xl[q];
        atomicAdd(&agg[q], make_float4(ex*a.x, ex*a.y, ex*a.z, ex*a.w));
    }
}

// Layer 2 epilogue: normalize + bias + LayerNorm -> output. Thread per node.
__global__ void k_finish2(const float* __restrict__ bias2,
                          const float* __restrict__ g2,
                          const float* __restrict__ beta2,
                          float* __restrict__ out) {
    int n = blockIdx.x * blockDim.x + threadIdx.x;
    if (n >= Nn) return;
    float inv = 1.f / (g_denom2[n] + 1e-16f);
    const float* agg = (const float*)&g_agg2[n * 4];
    float z[16];
    float mu = 0.f;
    #pragma unroll
    for (int c = 0; c < 16; c++) { z[c] = agg[c] * inv + bias2[c]; mu += z[c]; }
    mu *= (1.f / 16.f);
    float var = 0.f;
    #pragma unroll
    for (int c = 0; c < 16; c++) { float dd = z[c] - mu; var += dd * dd; }
    var *= (1.f / 16.f);
    float r = rsqrtf(var + LNEPS);
    #pragma unroll
    for (int c = 0; c < 16; c++)
        out[n * 16 + c] = (z[c] - mu) * r * g2[c] + beta2[c];
}

// ---------------- launch ----------------
extern "C" void kernel_launch(void* const* d_in, const int* in_sizes, int n_in,
                              void* d_out, int out_size) {
    const float* x     = (const float*)d_in[0];
    const void*  ei    = d_in[1];
    const float* ea    = (const float*)d_in[2];
    const float* W1l   = (const float*)d_in[3];
    const float* b1l   = (const float*)d_in[4];
    const float* W1r   = (const float*)d_in[5];
    const float* b1r   = (const float*)d_in[6];
    const float* We1   = (const float*)d_in[7];
    const float* att1  = (const float*)d_in[8];
    const float* bias1 = (const float*)d_in[9];
    const float* g1    = (const float*)d_in[10];
    const float* beta1 = (const float*)d_in[11];
    const float* W2l   = (const float*)d_in[12];
    const float* b2l   = (const float*)d_in[13];
    const float* W2r   = (const float*)d_in[14];
    const float* b2r   = (const float*)d_in[15];
    const float* We2   = (const float*)d_in[16];
    const float* att2  = (const float*)d_in[17];
    const float* bias2 = (const float*)d_in[18];
    const float* g2    = (const float*)d_in[19];
    const float* beta2 = (const float*)d_in[20];
    float* out = (float*)d_out;

    const int TB = 256;
    const int EB = (Ee + TB - 1) / TB;

    k_detect<<<1, 1>>>((const unsigned*)ei);
    k_decode<<<EB, TB>>>(ei);
    k_zero<<<4096, TB>>>();

    k_edge_logits1<<<EB, TB>>>(x, ea, W1l, b1l, W1r, b1r, We1, att1);
    k_edge_agg1<<<EB, TB>>>(x, W1l, b1l);
    k_finish1<<<(Nn * 32) / TB, TB>>>(bias1, g1, beta1);

    k_transform2<<<(Nn * 16 + TB - 1) / TB, TB>>>(W2l, b2l, W2r, b2r);
    k_edge_logits2<<<EB, TB>>>(ea, We2, att2);
    k_edge_agg2<<<EB, TB>>>();
    k_finish2<<<(Nn + TB - 1) / TB, TB>>>(bias2, g2, beta2, out);
}